// round 16
// baseline (speedup 1.0000x reference)
#include <cuda_runtime.h>
#include <math_constants.h>

// KNN min-dist, 9x9 window, C=3, zero-padded.
// d^2 = |t|^2 + (|o|^2 - 2 t.o), q=|o|^2 in float4.w -> 3 FFMA + 1 FMNMX/shift.
// R13 base (MLP-batched prologue, flat (dj,r) unroll, dual min acc) with the
// load lookahead deepened 2 -> 4 (ring of 5) to cover LDS latency in-warp.
// launch_bounds(128,6) -> 85-reg budget. Fixed shapes: B=4, C=3, H=256, W=512.

#define BDIM 128
#define TW 32
#define TH 16
#define TY 4
#define HALO 4
#define SW 9

#define B_ 4
#define H_ 256
#define W_ 512
#define HW_ (H_*W_)

#define SH_H (TH + 2*HALO)   // 24
#define SH_W (TW + 2*HALO)   // 40
#define NR (TY + SW - 1)     // 12
#define NITER (SW * NR)      // 108
#define NELEM (SH_H * SH_W)  // 960
#define LA 4                 // lookahead depth
#define RING (LA + 1)        // 5

__global__ __launch_bounds__(BDIM, 6) void knn_min_kernel(
    const float* __restrict__ tfm, const float* __restrict__ obs,
    float* __restrict__ out)
{
    __shared__ float4 s4[SH_H][SH_W];   // (o0, o1, o2, |o|^2)

    const int b  = blockIdx.z;
    const int x0 = blockIdx.x * TW;
    const int y0 = blockIdx.y * TH;
    const int tid = threadIdx.x;
    const int tx = tid & 31;
    const int ty = tid >> 5;

    const float* obs_b = obs + b * 3 * HW_;
    const float* tfm_b = tfm + b * 3 * HW_;

    // ---- prologue: tfm LDGs first (longest dependence chain to mainloop) ----
    const int ybase = y0 + ty * TY;
    const int xg = x0 + tx;
    float ta[TY], tc[TY], te[TY];
#pragma unroll
    for (int k = 0; k < TY; k++) {
        int g = (ybase + k) * W_ + xg;
        ta[k] = tfm_b[g];
        tc[k] = tfm_b[HW_ + g];
        te[k] = tfm_b[2 * HW_ + g];
    }

    // ---- phase 1: batch ALL obs LDGs (MLP ~24) ----
    float v0[8], v1[8], v2[8];
#pragma unroll
    for (int l = 0; l < 8; l++) {
        int idx = tid + l * BDIM;
        int iy = idx / SH_W;
        int ix = idx - iy * SH_W;
        int gy = y0 - HALO + iy;
        int gx = x0 - HALO + ix;
        bool ok = (idx < NELEM) & (gy >= 0) & (gy < H_) & (gx >= 0) & (gx < W_);
        int g = gy * W_ + gx;
        v0[l] = ok ? obs_b[g] : 0.f;
        v1[l] = ok ? obs_b[HW_ + g] : 0.f;
        v2[l] = ok ? obs_b[2 * HW_ + g] : 0.f;
    }
    // ---- phase 2: q + STS ----
#pragma unroll
    for (int l = 0; l < 8; l++) {
        int idx = tid + l * BDIM;
        if (idx < NELEM) {
            int iy = idx / SH_W;
            int ix = idx - iy * SH_W;
            float q = fmaf(v2[l], v2[l], fmaf(v1[l], v1[l], v0[l] * v0[l]));
            s4[iy][ix] = make_float4(v0[l], v1[l], v2[l], q);
        }
    }
    __syncthreads();

    // ---- per-pixel constants: nt_c = -2 t_c, tt = |t|^2 ----
    float nt0[TY], nt1[TY], nt2[TY], tt[TY], m0[TY], m1[TY];
#pragma unroll
    for (int k = 0; k < TY; k++) {
        nt0[k] = -2.f * ta[k];
        nt1[k] = -2.f * tc[k];
        nt2[k] = -2.f * te[k];
        tt[k]  = fmaf(te[k], te[k], fmaf(tc[k], tc[k], ta[k] * ta[k]));
        m0[k] = CUDART_INF_F;
        m1[k] = CUDART_INF_F;
    }

    // Flat base: iteration i -> dj = i/NR, r = i%NR, word offset r*SH_W + dj.
    const float4* base = &s4[ty * TY][tx];
#define OFF(i) (((i) % NR) * SH_W + ((i) / NR))

    float4 buf[RING];
#pragma unroll
    for (int p = 0; p < LA; p++)
        buf[p] = base[OFF(p)];

#pragma unroll
    for (int i = 0; i < NITER; i++) {
        if (i + LA < NITER)
            buf[(i + LA) % RING] = base[OFF(i + LA)];
        const float4 v = buf[i % RING];
        const int dj = i / NR;
        const int r  = i % NR;
#pragma unroll
        for (int k = 0; k < TY; k++) {
            const int di = r - k;
            if (di >= 0 && di < SW) {
                float e = fmaf(nt0[k], v.x,
                          fmaf(nt1[k], v.y,
                          fmaf(nt2[k], v.z, v.w)));
                if (dj & 1) m1[k] = fminf(m1[k], e);
                else        m0[k] = fminf(m0[k], e);
            }
        }
    }
#undef OFF

    float* out_b = out + b * HW_;
#pragma unroll
    for (int k = 0; k < TY; k++) {
        float m = fminf(m0[k], m1[k]);
        out_b[(ybase + k) * W_ + xg] = sqrtf(fmaxf(tt[k] + m, 0.f));
    }
}

extern "C" void kernel_launch(void* const* d_in, const int* in_sizes, int n_in,
                              void* d_out, int out_size)
{
    const float* tfm = (const float*)d_in[0];
    const float* obs = (const float*)d_in[1];
    float* out = (float*)d_out;
    (void)in_sizes; (void)n_in; (void)out_size;

    dim3 grid(W_ / TW, H_ / TH, B_);   // 16 x 16 x 4 = 1024 blocks
    dim3 block(BDIM);
    knn_min_kernel<<<grid, block>>>(tfm, obs, out);
}